// round 10
// baseline (speedup 1.0000x reference)
#include <cuda_runtime.h>
#include <cuda_bf16.h>
#include <cstdint>

// ---------------- problem constants ----------------
#define LSEQ 4096
#define HDIM 512
#define PDIM 256
#define N2P  512          // 2*PDIM (re/im interleaved)
#define KDIM 512
#define TCH  64           // scan chunk length
#define NCH  (LSEQ/TCH)   // 64 chunks
#define MAXB 8

// ---------------- scratch (no allocations allowed) ----------------
__device__ __align__(16) float  g_buf[(size_t)MAXB * LSEQ * N2P];        // Bu fp32
__device__ __align__(16) __nv_bfloat16 g_xh[(size_t)MAXB * LSEQ * HDIM]; // x hi
__device__ __align__(16) __nv_bfloat16 g_xl[(size_t)MAXB * LSEQ * HDIM]; // x lo
__device__ __align__(16) __nv_bfloat16 g_sh[(size_t)MAXB * LSEQ * N2P];  // xs hi
__device__ __align__(16) __nv_bfloat16 g_sl[(size_t)MAXB * LSEQ * N2P];  // xs lo
__device__ float2 g_carry[(size_t)MAXB * NCH * PDIM];
__device__ float2 g_A[PDIM];
__device__ float2 g_AT[PDIM];          // Lambda_bar^TCH
__device__ float2 g_coef[PDIM];
__device__ __align__(16) __nv_bfloat16 g_W1h[(size_t)N2P * KDIM];   // [n=2p][k=h]
__device__ __align__(16) __nv_bfloat16 g_W1l[(size_t)N2P * KDIM];
__device__ __align__(16) __nv_bfloat16 g_W2h[(size_t)HDIM * KDIM];  // [n=h][k=2p]
__device__ __align__(16) __nv_bfloat16 g_W2l[(size_t)HDIM * KDIM];

// ---------------- small device helpers ----------------
__device__ __forceinline__ uint32_t smem_u32(const void* p) {
    uint32_t a;
    asm("{ .reg .u64 t; cvta.to.shared.u64 t, %1; cvt.u32.u64 %0, t; }"
        : "=r"(a) : "l"(p));
    return a;
}
__device__ __forceinline__ void cpasync16(uint32_t dst, const void* src) {
    asm volatile("cp.async.cg.shared.global [%0], [%1], 16;"
                 :: "r"(dst), "l"(src) : "memory");
}
__device__ __forceinline__ void cp_commit() {
    asm volatile("cp.async.commit_group;" ::: "memory");
}
template<int N>
__device__ __forceinline__ void cp_wait() {
    asm volatile("cp.async.wait_group %0;" :: "n"(N) : "memory");
}
__device__ __forceinline__ void ldsm4(uint32_t* r, uint32_t addr) {
    asm volatile("ldmatrix.sync.aligned.m8n8.x4.shared.b16 {%0,%1,%2,%3}, [%4];"
        : "=r"(r[0]), "=r"(r[1]), "=r"(r[2]), "=r"(r[3]) : "r"(addr));
}
__device__ __forceinline__ void mma16816(float* d, const uint32_t* a,
                                         uint32_t b0, uint32_t b1) {
    asm volatile(
        "mma.sync.aligned.m16n8k16.row.col.f32.bf16.bf16.f32 "
        "{%0,%1,%2,%3}, {%4,%5,%6,%7}, {%8,%9}, {%0,%1,%2,%3};"
        : "+f"(d[0]), "+f"(d[1]), "+f"(d[2]), "+f"(d[3])
        : "r"(a[0]), "r"(a[1]), "r"(a[2]), "r"(a[3]), "r"(b0), "r"(b1));
}
__device__ __forceinline__ void split2(float v, __nv_bfloat16& h, __nv_bfloat16& l) {
    h = __float2bfloat16(v);
    l = __float2bfloat16(v - __bfloat162float(h));
}
#define SWZ(o) ((o) ^ (((o) >> 3) & 0x70))

// ---------------- precompute scalars (1 block) ----------------
__global__ void k_precomp_scalar(const float* __restrict__ Lre,
                                 const float* __restrict__ Lim,
                                 const float* __restrict__ lstep) {
    int p = threadIdx.x;
    if (p >= PDIM) return;
    double lr = (double)Lre[p], li = (double)Lim[p];
    float stepf = (float)exp((double)lstep[p]);
    float arf = (float)(lr * (double)stepf);
    float aif = (float)(li * (double)stepf);
    float erf_ = (float)exp((double)arf);
    float cf  = (float)cos((double)aif);
    float sf  = (float)sin((double)aif);
    float2 a = make_float2(erf_ * cf, erf_ * sf);
    g_A[p] = a;
    double ax = (double)a.x, ay = (double)a.y;
    #pragma unroll
    for (int i = 0; i < 6; i++) {          // TCH = 64 = 2^6
        double nx = ax * ax - ay * ay;
        double ny = 2.0 * ax * ay;
        ax = nx; ay = ny;
    }
    g_AT[p] = make_float2((float)ax, (float)ay);
    double nr = (double)a.x - 1.0, ni = (double)a.y;
    double den = lr * lr + li * li;
    g_coef[p] = make_float2((float)((nr * lr + ni * li) / den),
                            (float)((ni * lr - nr * li) / den));
}

// ---------------- build bf16 hi/lo weights, N-major [n][k] ----------------
__global__ void k_precomp_w(const float* __restrict__ Bin,
                            const float* __restrict__ Cin) {
    int t = blockIdx.x * blockDim.x + threadIdx.x;   // over H*P
    if (t >= HDIM * PDIM) return;
    int h = t / PDIM, p = t % PDIM;
    float2 cf = g_coef[p];
    float br = Bin[(p * HDIM + h) * 2 + 0];
    float bi = Bin[(p * HDIM + h) * 2 + 1];
    float wre = cf.x * br - cf.y * bi;
    float wim = cf.x * bi + cf.y * br;
    split2(wre, g_W1h[(size_t)(2 * p) * KDIM + h], g_W1l[(size_t)(2 * p) * KDIM + h]);
    split2(wim, g_W1h[(size_t)(2 * p + 1) * KDIM + h], g_W1l[(size_t)(2 * p + 1) * KDIM + h]);
    float cr = Cin[(h * PDIM + p) * 2 + 0];
    float ci = Cin[(h * PDIM + p) * 2 + 1];
    split2( 2.0f * cr, g_W2h[(size_t)h * KDIM + 2 * p],     g_W2l[(size_t)h * KDIM + 2 * p]);
    split2(-2.0f * ci, g_W2h[(size_t)h * KDIM + 2 * p + 1], g_W2l[(size_t)h * KDIM + 2 * p + 1]);
}

// ---------------- x -> bf16 hi/lo ----------------
__global__ void k_cvt_x(const float* __restrict__ x, int n4) {
    int i = blockIdx.x * blockDim.x + threadIdx.x;
    if (i >= n4) return;
    float4 v = ((const float4*)x)[i];
    __nv_bfloat16 h0, h1, h2, h3, l0, l1, l2, l3;
    split2(v.x, h0, l0); split2(v.y, h1, l1);
    split2(v.z, h2, l2); split2(v.w, h3, l3);
    __nv_bfloat162 ph0 = __nv_bfloat162(h0, h1), ph1 = __nv_bfloat162(h2, h3);
    __nv_bfloat162 pl0 = __nv_bfloat162(l0, l1), pl1 = __nv_bfloat162(l2, l3);
    ((uint2*)g_xh)[i] = make_uint2(*(uint32_t*)&ph0, *(uint32_t*)&ph1);
    ((uint2*)g_xl)[i] = make_uint2(*(uint32_t*)&pl0, *(uint32_t*)&pl1);
}

// ---------------- mma.sync bf16 split GEMM: C[M,512] = A @ W^T (+ D*x) -------
// A: bf16 hi/lo [M][512] row-major; W: bf16 hi/lo [512][512] N-major [n][k].
// 128x128 CTA tile, K-chunk 32. Stage (32KB): A rows 0..127 of 128B
//   [Ah 64B | Al 64B], then W rows [Wh 64B | Wl 64B] at +16KB.
// 3-stage cp.async pipeline, SW128 swizzle, ldmatrix fragments,
// 256 threads = 8 warps, warp tile 32(M) x 64(N), 2 CTAs/SM.
#define GSTG 32768
#define NSTG 3
#define GSMT (NSTG * GSTG)
#define NKCH (KDIM / 32)   // 16 chunks

template<int EPI>
__global__ void __launch_bounds__(256, 2)
k_mmagemm(const __nv_bfloat16* __restrict__ Ahg, const __nv_bfloat16* __restrict__ Alg,
          const __nv_bfloat16* __restrict__ Whg, const __nv_bfloat16* __restrict__ Wlg,
          float* __restrict__ Cg, const float* __restrict__ Dv,
          const float* __restrict__ Xg) {
    extern __shared__ __align__(128) char smem[];
    uint32_t sb = smem_u32(smem);
    int tid = threadIdx.x, wid = tid >> 5, lid = tid & 31;
    int g = lid >> 2, t = lid & 3;
    int wm = (wid & 3) * 32, wn = (wid >> 2) * 64;
    size_t brow = (size_t)blockIdx.y * 128;
    size_t bcol = (size_t)blockIdx.x * 128;

    // gmem -> smem: thread (lrow, lhalf): 64B from hi or lo array into one row
    int lrow = tid >> 1, lhalf = tid & 1;
    const char* srcA = (const char*)((lhalf ? Alg : Ahg) + (brow + lrow) * KDIM);
    const char* srcW = (const char*)((lhalf ? Wlg : Whg) + (bcol + lrow) * KDIM);
    uint32_t dbase = (uint32_t)lrow * 128 + (uint32_t)lhalf * 64;

    // ldmatrix lane addressing
    int r15 = lid & 15;
    uint32_t c16 = ((uint32_t)(lid >> 4)) * 16;
    uint32_t xr  = ((uint32_t)(lid & 7)) * 16;

    float acc[2][8][4];
    #pragma unroll
    for (int mt = 0; mt < 2; mt++)
        #pragma unroll
        for (int nt = 0; nt < 8; nt++)
            #pragma unroll
            for (int j = 0; j < 4; j++) acc[mt][nt][j] = 0.f;

    auto load_stage = [&](int c, int s) {
        uint32_t st = sb + (uint32_t)s * GSTG;
        size_t ko = (size_t)c * 64;   // 32 bf16 = 64 bytes along K
        #pragma unroll
        for (int i = 0; i < 4; i++) {
            uint32_t d = SWZ(dbase + i * 16);
            cpasync16(st +         d, srcA + ko + i * 16);
            cpasync16(st + 16384 + d, srcW + ko + i * 16);
        }
        cp_commit();
    };

    auto compute_stage = [&](int s) {
        uint32_t stA = sb + (uint32_t)s * GSTG;
        uint32_t stB = stA + 16384;
        #pragma unroll
        for (int ks = 0; ks < 2; ks++) {
            uint32_t colh = ((uint32_t)ks * 32 + c16) ^ xr;         // hi bytes [0,64)
            uint32_t coll = ((64u + (uint32_t)ks * 32 + c16) ^ xr); // lo bytes [64,128)
            uint32_t ah[2][4], al[2][4];
            #pragma unroll
            for (int mt = 0; mt < 2; mt++) {
                uint32_t rb = stA + (uint32_t)(wm + mt * 16 + r15) * 128;
                ldsm4(ah[mt], rb + colh);
                ldsm4(al[mt], rb + coll);
            }
            #pragma unroll
            for (int pr = 0; pr < 4; pr++) {
                uint32_t bh[4], bl[4];
                uint32_t rb = stB + (uint32_t)(wn + pr * 16 + r15) * 128;
                ldsm4(bh, rb + colh);
                ldsm4(bl, rb + coll);
                #pragma unroll
                for (int mt = 0; mt < 2; mt++)
                    #pragma unroll
                    for (int sub = 0; sub < 2; sub++) {
                        float* d = acc[mt][pr * 2 + sub];
                        mma16816(d, ah[mt], bh[sub], bh[sub + 2]);
                        mma16816(d, ah[mt], bl[sub], bl[sub + 2]);
                        mma16816(d, al[mt], bh[sub], bh[sub + 2]);
                    }
            }
        }
    };

    // 3-stage pipeline over 16 K-chunks
    load_stage(0, 0);
    load_stage(1, 1);
    cp_wait<1>();
    __syncthreads();
    #pragma unroll 1
    for (int c = 0; c < NKCH; c++) {
        if (c + 2 < NKCH) load_stage(c + 2, (c + 2) % NSTG);
        compute_stage(c % NSTG);
        if (c + 1 < NKCH) {
            cp_wait<1>();
            __syncthreads();
        }
    }

    // epilogue: accum -> gmem fp32 (+ D*x)
    #pragma unroll
    for (int mt = 0; mt < 2; mt++) {
        size_t r0 = brow + wm + mt * 16 + g;
        size_t r1 = r0 + 8;
        #pragma unroll
        for (int nt = 0; nt < 8; nt++) {
            size_t col = bcol + wn + nt * 8 + t * 2;
            float2 v0 = make_float2(acc[mt][nt][0], acc[mt][nt][1]);
            float2 v1 = make_float2(acc[mt][nt][2], acc[mt][nt][3]);
            if (EPI) {
                float2 d  = *(const float2*)(Dv + col);
                float2 x0 = *(const float2*)(Xg + r0 * 512 + col);
                float2 x1 = *(const float2*)(Xg + r1 * 512 + col);
                v0.x = fmaf(d.x, x0.x, v0.x); v0.y = fmaf(d.y, x0.y, v0.y);
                v1.x = fmaf(d.x, x1.x, v1.x); v1.y = fmaf(d.y, x1.y, v1.y);
            }
            *(float2*)(Cg + r0 * 512 + col) = v0;
            *(float2*)(Cg + r1 * 512 + col) = v1;
        }
    }
}

// ---------------- chunk carry pass (read-only over Bu) ----------------
__global__ void k_scan_carry() {
    int p  = threadIdx.x;
    int ch = blockIdx.x;
    int b  = blockIdx.y;
    float2 a = g_A[p];
    const float2* buf = (const float2*)g_buf;
    size_t base = ((size_t)b * LSEQ + (size_t)ch * TCH) * PDIM + p;
    float sx = 0.f, sy = 0.f;
    #pragma unroll 4
    for (int i = 0; i < TCH; i++) {
        float2 v = buf[base + (size_t)i * PDIM];
        float nx = fmaf(a.x, sx, fmaf(-a.y, sy, v.x));
        float ny = fmaf(a.x, sy, fmaf( a.y, sx, v.y));
        sx = nx; sy = ny;
    }
    g_carry[((size_t)b * NCH + ch) * PDIM + p] = make_float2(sx, sy);
}

// ---------------- exclusive scan over chunk carries ----------------
__global__ void k_scan_carries() {
    int p = threadIdx.x;
    int b = blockIdx.x;
    float2 aT = g_AT[p];
    float sx = 0.f, sy = 0.f;
    for (int j = 0; j < NCH; j++) {
        size_t idx = ((size_t)b * NCH + j) * PDIM + p;
        float2 t = g_carry[idx];
        g_carry[idx] = make_float2(sx, sy);
        float nx = fmaf(aT.x, sx, fmaf(-aT.y, sy, t.x));
        float ny = fmaf(aT.x, sy, fmaf( aT.y, sx, t.y));
        sx = nx; sy = ny;
    }
}

// ---------------- full local scan seeded by carry + convert to bf16 ---------
__global__ void k_fixup_cvt() {
    int p  = threadIdx.x;
    int ch = blockIdx.x;
    int b  = blockIdx.y;
    float2 s = g_carry[((size_t)b * NCH + ch) * PDIM + p];   // exclusive prefix
    float2 a = g_A[p];
    const float2* buf = (const float2*)g_buf;
    size_t rbase = (size_t)b * LSEQ + (size_t)ch * TCH;
    #pragma unroll 4
    for (int i = 0; i < TCH; i++) {
        float2 v = buf[(rbase + i) * PDIM + p];
        float nx = fmaf(a.x, s.x, fmaf(-a.y, s.y, v.x));
        float ny = fmaf(a.x, s.y, fmaf( a.y, s.x, v.y));
        s.x = nx; s.y = ny;
        __nv_bfloat16 hr, lr, hi, li;
        split2(s.x, hr, lr);
        split2(s.y, hi, li);
        __nv_bfloat162 ph = __nv_bfloat162(hr, hi);
        __nv_bfloat162 pl = __nv_bfloat162(lr, li);
        size_t o = (rbase + i) * N2P + 2 * p;
        *(uint32_t*)(g_sh + o) = *(uint32_t*)&ph;
        *(uint32_t*)(g_sl + o) = *(uint32_t*)&pl;
    }
}

// ---------------- launch ----------------
extern "C" void kernel_launch(void* const* d_in, const int* in_sizes, int n_in,
                              void* d_out, int out_size) {
    const float* x   = (const float*)d_in[0];
    const float* Lre = (const float*)d_in[1];
    const float* Lim = (const float*)d_in[2];
    const float* Bin = (const float*)d_in[3];
    const float* Cin = (const float*)d_in[4];
    const float* Dv  = (const float*)d_in[5];
    const float* ls  = (const float*)d_in[6];
    float* y = (float*)d_out;
    (void)n_in; (void)out_size;

    int Bsz = in_sizes[0] / (LSEQ * HDIM);
    if (Bsz > MAXB) Bsz = MAXB;
    int M = Bsz * LSEQ;

    float *bufp = nullptr;
    __nv_bfloat16 *xh, *xl, *sh, *sl, *w1h, *w1l, *w2h, *w2l;
    cudaGetSymbolAddress((void**)&bufp, g_buf);
    cudaGetSymbolAddress((void**)&xh,  g_xh);
    cudaGetSymbolAddress((void**)&xl,  g_xl);
    cudaGetSymbolAddress((void**)&sh,  g_sh);
    cudaGetSymbolAddress((void**)&sl,  g_sl);
    cudaGetSymbolAddress((void**)&w1h, g_W1h);
    cudaGetSymbolAddress((void**)&w1l, g_W1l);
    cudaGetSymbolAddress((void**)&w2h, g_W2h);
    cudaGetSymbolAddress((void**)&w2l, g_W2l);

    cudaFuncSetAttribute(k_mmagemm<0>, cudaFuncAttributeMaxDynamicSharedMemorySize, GSMT);
    cudaFuncSetAttribute(k_mmagemm<1>, cudaFuncAttributeMaxDynamicSharedMemorySize, GSMT);

    k_precomp_scalar<<<1, 256>>>(Lre, Lim, ls);
    k_precomp_w<<<(HDIM * PDIM + 255) / 256, 256>>>(Bin, Cin);

    int n4 = M * HDIM / 4;
    k_cvt_x<<<(n4 + 255) / 256, 256>>>(x, n4);

    // GEMM1: Bu = x @ W1  -> g_buf (fp32)
    dim3 g1(N2P / 128, M / 128);
    k_mmagemm<0><<<g1, 256, GSMT>>>(xh, xl, w1h, w1l, bufp, nullptr, nullptr);

    // scan
    dim3 gs(NCH, Bsz);
    k_scan_carry<<<gs, PDIM>>>();
    k_scan_carries<<<Bsz, PDIM>>>();
    k_fixup_cvt<<<gs, PDIM>>>();

    // GEMM2: y = xs @ W2 + D*x
    dim3 g2(HDIM / 128, M / 128);
    k_mmagemm<1><<<g2, 256, GSMT>>>(sh, sl, w2h, w2l, y, Dv, x);
}

// round 11
// speedup vs baseline: 1.1344x; 1.1344x over previous
#include <cuda_runtime.h>
#include <cuda_bf16.h>
#include <cstdint>

// ---------------- problem constants ----------------
#define LSEQ 4096
#define HDIM 512
#define PDIM 256
#define N2P  512          // 2*PDIM (re/im interleaved)
#define KDIM 512
#define TCH  64           // scan chunk length
#define NCH  (LSEQ/TCH)   // 64 chunks
#define MAXB 8

// ---------------- scratch (no allocations allowed) ----------------
__device__ __align__(16) float  g_buf[(size_t)MAXB * LSEQ * N2P];        // Bu fp32
__device__ __align__(16) __nv_bfloat16 g_xh[(size_t)MAXB * LSEQ * HDIM]; // x hi
__device__ __align__(16) __nv_bfloat16 g_xl[(size_t)MAXB * LSEQ * HDIM]; // x lo
__device__ __align__(16) __nv_bfloat16 g_sh[(size_t)MAXB * LSEQ * N2P];  // xs hi
__device__ __align__(16) __nv_bfloat16 g_sl[(size_t)MAXB * LSEQ * N2P];  // xs lo
__device__ float2 g_carry[(size_t)MAXB * NCH * PDIM];
__device__ float2 g_A[PDIM];
__device__ float2 g_AT[PDIM];          // Lambda_bar^TCH
__device__ float2 g_coef[PDIM];
__device__ __align__(16) __nv_bfloat16 g_W1h[(size_t)N2P * KDIM];   // [n=2p][k=h]
__device__ __align__(16) __nv_bfloat16 g_W1l[(size_t)N2P * KDIM];
__device__ __align__(16) __nv_bfloat16 g_W2h[(size_t)HDIM * KDIM];  // [n=h][k=2p]
__device__ __align__(16) __nv_bfloat16 g_W2l[(size_t)HDIM * KDIM];

// ---------------- small device helpers ----------------
__device__ __forceinline__ uint32_t smem_u32(const void* p) {
    uint32_t a;
    asm("{ .reg .u64 t; cvta.to.shared.u64 t, %1; cvt.u32.u64 %0, t; }"
        : "=r"(a) : "l"(p));
    return a;
}
__device__ __forceinline__ void cpasync16(uint32_t dst, const void* src) {
    asm volatile("cp.async.cg.shared.global [%0], [%1], 16;"
                 :: "r"(dst), "l"(src) : "memory");
}
__device__ __forceinline__ void cp_commit() {
    asm volatile("cp.async.commit_group;" ::: "memory");
}
template<int N>
__device__ __forceinline__ void cp_wait() {
    asm volatile("cp.async.wait_group %0;" :: "n"(N) : "memory");
}
__device__ __forceinline__ void ldsm4(uint32_t* r, uint32_t addr) {
    asm volatile("ldmatrix.sync.aligned.m8n8.x4.shared.b16 {%0,%1,%2,%3}, [%4];"
        : "=r"(r[0]), "=r"(r[1]), "=r"(r[2]), "=r"(r[3]) : "r"(addr));
}
__device__ __forceinline__ void mma16816(float* d, const uint32_t* a,
                                         uint32_t b0, uint32_t b1) {
    asm volatile(
        "mma.sync.aligned.m16n8k16.row.col.f32.bf16.bf16.f32 "
        "{%0,%1,%2,%3}, {%4,%5,%6,%7}, {%8,%9}, {%0,%1,%2,%3};"
        : "+f"(d[0]), "+f"(d[1]), "+f"(d[2]), "+f"(d[3])
        : "r"(a[0]), "r"(a[1]), "r"(a[2]), "r"(a[3]), "r"(b0), "r"(b1));
}
__device__ __forceinline__ void split2(float v, __nv_bfloat16& h, __nv_bfloat16& l) {
    h = __float2bfloat16(v);
    l = __float2bfloat16(v - __bfloat162float(h));
}
#define SWZ(o) ((o) ^ (((o) >> 3) & 0x70))

// ---------------- precompute scalars (1 block) ----------------
__global__ void k_precomp_scalar(const float* __restrict__ Lre,
                                 const float* __restrict__ Lim,
                                 const float* __restrict__ lstep) {
    int p = threadIdx.x;
    if (p >= PDIM) return;
    double lr = (double)Lre[p], li = (double)Lim[p];
    float stepf = (float)exp((double)lstep[p]);
    float arf = (float)(lr * (double)stepf);
    float aif = (float)(li * (double)stepf);
    float erf_ = (float)exp((double)arf);
    float cf  = (float)cos((double)aif);
    float sf  = (float)sin((double)aif);
    float2 a = make_float2(erf_ * cf, erf_ * sf);
    g_A[p] = a;
    double ax = (double)a.x, ay = (double)a.y;
    #pragma unroll
    for (int i = 0; i < 6; i++) {          // TCH = 64 = 2^6
        double nx = ax * ax - ay * ay;
        double ny = 2.0 * ax * ay;
        ax = nx; ay = ny;
    }
    g_AT[p] = make_float2((float)ax, (float)ay);
    double nr = (double)a.x - 1.0, ni = (double)a.y;
    double den = lr * lr + li * li;
    g_coef[p] = make_float2((float)((nr * lr + ni * li) / den),
                            (float)((ni * lr - nr * li) / den));
}

// ---------------- build bf16 hi/lo weights, N-major [n][k] ----------------
__global__ void k_precomp_w(const float* __restrict__ Bin,
                            const float* __restrict__ Cin) {
    int t = blockIdx.x * blockDim.x + threadIdx.x;   // over H*P
    if (t >= HDIM * PDIM) return;
    int h = t / PDIM, p = t % PDIM;
    float2 cf = g_coef[p];
    float br = Bin[(p * HDIM + h) * 2 + 0];
    float bi = Bin[(p * HDIM + h) * 2 + 1];
    float wre = cf.x * br - cf.y * bi;
    float wim = cf.x * bi + cf.y * br;
    split2(wre, g_W1h[(size_t)(2 * p) * KDIM + h], g_W1l[(size_t)(2 * p) * KDIM + h]);
    split2(wim, g_W1h[(size_t)(2 * p + 1) * KDIM + h], g_W1l[(size_t)(2 * p + 1) * KDIM + h]);
    float cr = Cin[(h * PDIM + p) * 2 + 0];
    float ci = Cin[(h * PDIM + p) * 2 + 1];
    split2( 2.0f * cr, g_W2h[(size_t)h * KDIM + 2 * p],     g_W2l[(size_t)h * KDIM + 2 * p]);
    split2(-2.0f * ci, g_W2h[(size_t)h * KDIM + 2 * p + 1], g_W2l[(size_t)h * KDIM + 2 * p + 1]);
}

// ---------------- x -> bf16 hi/lo ----------------
__global__ void k_cvt_x(const float* __restrict__ x, int n4) {
    int i = blockIdx.x * blockDim.x + threadIdx.x;
    if (i >= n4) return;
    float4 v = ((const float4*)x)[i];
    __nv_bfloat16 h0, h1, h2, h3, l0, l1, l2, l3;
    split2(v.x, h0, l0); split2(v.y, h1, l1);
    split2(v.z, h2, l2); split2(v.w, h3, l3);
    __nv_bfloat162 ph0 = __nv_bfloat162(h0, h1), ph1 = __nv_bfloat162(h2, h3);
    __nv_bfloat162 pl0 = __nv_bfloat162(l0, l1), pl1 = __nv_bfloat162(l2, l3);
    ((uint2*)g_xh)[i] = make_uint2(*(uint32_t*)&ph0, *(uint32_t*)&ph1);
    ((uint2*)g_xl)[i] = make_uint2(*(uint32_t*)&pl0, *(uint32_t*)&pl1);
}

// ---------------- mma.sync bf16 split GEMM: C[M,512] = A @ W^T (+ D*x) -------
// A: bf16 hi/lo [M][512] row-major; W: bf16 hi/lo [512][512] N-major [n][k].
// 128x128 CTA tile, K-chunk 64, 3-stage cp.async pipeline, SW128 smem,
// ldmatrix fragment loads. 256 threads = 8 warps, warp tile 32(M) x 64(N).
// Stage layout (64KB): Ah@0, Al@16K, Wh@32K, Wl@48K; 128 rows x 128B, swizzled.
#define GSTG 65536
#define GSMT (3 * GSTG)

template<int EPI>
__global__ void __launch_bounds__(256)
k_mmagemm(const __nv_bfloat16* __restrict__ Ahg, const __nv_bfloat16* __restrict__ Alg,
          const __nv_bfloat16* __restrict__ Whg, const __nv_bfloat16* __restrict__ Wlg,
          float* __restrict__ Cg, const float* __restrict__ Dv,
          const float* __restrict__ Xg) {
    extern __shared__ __align__(128) char smem[];
    uint32_t sb = smem_u32(smem);
    int tid = threadIdx.x, wid = tid >> 5, lid = tid & 31;
    int g = lid >> 2, t = lid & 3;
    int wm = (wid & 3) * 32, wn = (wid >> 2) * 64;
    size_t brow = (size_t)blockIdx.y * 128;
    size_t bcol = (size_t)blockIdx.x * 128;

    // gmem -> smem mapping: 2 threads per 128B row, 4 x 16B each
    int lrow = tid >> 1, lhalf = tid & 1;
    const char* srcAh = (const char*)(Ahg + (brow + lrow) * KDIM) + lhalf * 64;
    const char* srcAl = (const char*)(Alg + (brow + lrow) * KDIM) + lhalf * 64;
    const char* srcWh = (const char*)(Whg + (bcol + lrow) * KDIM) + lhalf * 64;
    const char* srcWl = (const char*)(Wlg + (bcol + lrow) * KDIM) + lhalf * 64;
    uint32_t dbase = (uint32_t)lrow * 128 + (uint32_t)lhalf * 64;

    // ldmatrix lane addressing: lane -> (row within 16, k-halfword)
    int r15 = lid & 15;
    uint32_t c16 = ((uint32_t)(lid >> 4)) * 16;   // matrices 2,3 take k bytes +16
    uint32_t xr  = ((uint32_t)(lid & 7)) * 16;    // SW128 row-phase XOR

    float acc[2][8][4];
    #pragma unroll
    for (int mt = 0; mt < 2; mt++)
        #pragma unroll
        for (int nt = 0; nt < 8; nt++)
            #pragma unroll
            for (int j = 0; j < 4; j++) acc[mt][nt][j] = 0.f;

    auto load_stage = [&](int c, int s) {
        uint32_t st = sb + (uint32_t)s * GSTG;
        size_t ko = (size_t)c * 128;   // 64 bf16 = 128B along K per chunk
        #pragma unroll
        for (int i = 0; i < 4; i++) {
            uint32_t d = SWZ(dbase + i * 16);
            cpasync16(st +         d, srcAh + ko + i * 16);
            cpasync16(st + 16384 + d, srcAl + ko + i * 16);
            cpasync16(st + 32768 + d, srcWh + ko + i * 16);
            cpasync16(st + 49152 + d, srcWl + ko + i * 16);
        }
        cp_commit();
    };

    auto compute_stage = [&](int s) {
        uint32_t st = sb + (uint32_t)s * GSTG;
        #pragma unroll
        for (int ks = 0; ks < 4; ks++) {
            uint32_t col = ((uint32_t)ks * 32 + c16) ^ xr;   // within 128B row
            uint32_t ah[2][4], al[2][4];
            #pragma unroll
            for (int mt = 0; mt < 2; mt++) {
                uint32_t rb = st + (uint32_t)(wm + mt * 16 + r15) * 128;
                ldsm4(ah[mt], rb + col);             // A hi
                ldsm4(al[mt], rb + 16384 + col);     // A lo
            }
            #pragma unroll
            for (int pr = 0; pr < 4; pr++) {
                uint32_t bh[4], bl[4];
                uint32_t rb = st + 32768 + (uint32_t)(wn + pr * 16 + r15) * 128;
                ldsm4(bh, rb + col);                 // W hi
                ldsm4(bl, rb + 16384 + col);         // W lo
                #pragma unroll
                for (int mt = 0; mt < 2; mt++)
                    #pragma unroll
                    for (int sub = 0; sub < 2; sub++) {
                        float* d = acc[mt][pr * 2 + sub];
                        mma16816(d, ah[mt], bh[sub], bh[sub + 2]);
                        mma16816(d, ah[mt], bl[sub], bl[sub + 2]);
                        mma16816(d, al[mt], bh[sub], bh[sub + 2]);
                    }
            }
        }
    };

    // 3-stage pipeline over 8 K-chunks
    load_stage(0, 0);
    load_stage(1, 1);
    cp_wait<1>();
    __syncthreads();
    #pragma unroll 1
    for (int c = 0; c < 8; c++) {
        if (c + 2 < 8) load_stage(c + 2, (c + 2) % 3);
        compute_stage(c % 3);
        if (c + 1 < 8) {
            cp_wait<1>();
            __syncthreads();
        }
    }

    // epilogue: accum -> gmem fp32 (+ D*x)
    #pragma unroll
    for (int mt = 0; mt < 2; mt++) {
        size_t r0 = brow + wm + mt * 16 + g;
        size_t r1 = r0 + 8;
        #pragma unroll
        for (int nt = 0; nt < 8; nt++) {
            size_t col = bcol + wn + nt * 8 + t * 2;
            float2 v0 = make_float2(acc[mt][nt][0], acc[mt][nt][1]);
            float2 v1 = make_float2(acc[mt][nt][2], acc[mt][nt][3]);
            if (EPI) {
                float2 d  = *(const float2*)(Dv + col);
                float2 x0 = *(const float2*)(Xg + r0 * 512 + col);
                float2 x1 = *(const float2*)(Xg + r1 * 512 + col);
                v0.x = fmaf(d.x, x0.x, v0.x); v0.y = fmaf(d.y, x0.y, v0.y);
                v1.x = fmaf(d.x, x1.x, v1.x); v1.y = fmaf(d.y, x1.y, v1.y);
            }
            *(float2*)(Cg + r0 * 512 + col) = v0;
            *(float2*)(Cg + r1 * 512 + col) = v1;
        }
    }
}

// ---------------- chunk carry pass (read-only over Bu) ----------------
__global__ void k_scan_carry() {
    int p  = threadIdx.x;
    int ch = blockIdx.x;
    int b  = blockIdx.y;
    float2 a = g_A[p];
    const float2* buf = (const float2*)g_buf;
    size_t base = ((size_t)b * LSEQ + (size_t)ch * TCH) * PDIM + p;
    float sx = 0.f, sy = 0.f;
    #pragma unroll 4
    for (int i = 0; i < TCH; i++) {
        float2 v = buf[base + (size_t)i * PDIM];
        float nx = fmaf(a.x, sx, fmaf(-a.y, sy, v.x));
        float ny = fmaf(a.x, sy, fmaf( a.y, sx, v.y));
        sx = nx; sy = ny;
    }
    g_carry[((size_t)b * NCH + ch) * PDIM + p] = make_float2(sx, sy);
}

// ---------------- exclusive scan over chunk carries ----------------
__global__ void k_scan_carries() {
    int p = threadIdx.x;
    int b = blockIdx.x;
    float2 aT = g_AT[p];
    float sx = 0.f, sy = 0.f;
    for (int j = 0; j < NCH; j++) {
        size_t idx = ((size_t)b * NCH + j) * PDIM + p;
        float2 t = g_carry[idx];
        g_carry[idx] = make_float2(sx, sy);
        float nx = fmaf(aT.x, sx, fmaf(-aT.y, sy, t.x));
        float ny = fmaf(aT.x, sy, fmaf( aT.y, sx, t.y));
        sx = nx; sy = ny;
    }
}

// ---------------- full local scan seeded by carry + convert to bf16 ---------
__global__ void k_fixup_cvt() {
    int p  = threadIdx.x;
    int ch = blockIdx.x;
    int b  = blockIdx.y;
    float2 s = g_carry[((size_t)b * NCH + ch) * PDIM + p];   // exclusive prefix
    float2 a = g_A[p];
    const float2* buf = (const float2*)g_buf;
    size_t rbase = (size_t)b * LSEQ + (size_t)ch * TCH;
    #pragma unroll 4
    for (int i = 0; i < TCH; i++) {
        float2 v = buf[(rbase + i) * PDIM + p];
        float nx = fmaf(a.x, s.x, fmaf(-a.y, s.y, v.x));
        float ny = fmaf(a.x, s.y, fmaf( a.y, s.x, v.y));
        s.x = nx; s.y = ny;
        __nv_bfloat16 hr, lr, hi, li;
        split2(s.x, hr, lr);
        split2(s.y, hi, li);
        __nv_bfloat162 ph = __nv_bfloat162(hr, hi);
        __nv_bfloat162 pl = __nv_bfloat162(lr, li);
        size_t o = (rbase + i) * N2P + 2 * p;
        *(uint32_t*)(g_sh + o) = *(uint32_t*)&ph;
        *(uint32_t*)(g_sl + o) = *(uint32_t*)&pl;
    }
}

// ---------------- launch ----------------
extern "C" void kernel_launch(void* const* d_in, const int* in_sizes, int n_in,
                              void* d_out, int out_size) {
    const float* x   = (const float*)d_in[0];
    const float* Lre = (const float*)d_in[1];
    const float* Lim = (const float*)d_in[2];
    const float* Bin = (const float*)d_in[3];
    const float* Cin = (const float*)d_in[4];
    const float* Dv  = (const float*)d_in[5];
    const float* ls  = (const float*)d_in[6];
    float* y = (float*)d_out;
    (void)n_in; (void)out_size;

    int Bsz = in_sizes[0] / (LSEQ * HDIM);
    if (Bsz > MAXB) Bsz = MAXB;
    int M = Bsz * LSEQ;

    float *bufp = nullptr;
    __nv_bfloat16 *xh, *xl, *sh, *sl, *w1h, *w1l, *w2h, *w2l;
    cudaGetSymbolAddress((void**)&bufp, g_buf);
    cudaGetSymbolAddress((void**)&xh,  g_xh);
    cudaGetSymbolAddress((void**)&xl,  g_xl);
    cudaGetSymbolAddress((void**)&sh,  g_sh);
    cudaGetSymbolAddress((void**)&sl,  g_sl);
    cudaGetSymbolAddress((void**)&w1h, g_W1h);
    cudaGetSymbolAddress((void**)&w1l, g_W1l);
    cudaGetSymbolAddress((void**)&w2h, g_W2h);
    cudaGetSymbolAddress((void**)&w2l, g_W2l);

    cudaFuncSetAttribute(k_mmagemm<0>, cudaFuncAttributeMaxDynamicSharedMemorySize, GSMT);
    cudaFuncSetAttribute(k_mmagemm<1>, cudaFuncAttributeMaxDynamicSharedMemorySize, GSMT);

    k_precomp_scalar<<<1, 256>>>(Lre, Lim, ls);
    k_precomp_w<<<(HDIM * PDIM + 255) / 256, 256>>>(Bin, Cin);

    int n4 = M * HDIM / 4;
    k_cvt_x<<<(n4 + 255) / 256, 256>>>(x, n4);

    // GEMM1: Bu = x @ W1  -> g_buf (fp32)
    dim3 g1(N2P / 128, M / 128);
    k_mmagemm<0><<<g1, 256, GSMT>>>(xh, xl, w1h, w1l, bufp, nullptr, nullptr);

    // scan
    dim3 gs(NCH, Bsz);
    k_scan_carry<<<gs, PDIM>>>();
    k_scan_carries<<<Bsz, PDIM>>>();
    k_fixup_cvt<<<gs, PDIM>>>();

    // GEMM2: y = xs @ W2 + D*x
    dim3 g2(HDIM / 128, M / 128);
    k_mmagemm<1><<<g2, 256, GSMT>>>(sh, sl, w2h, w2l, y, Dv, x);
}

// round 12
// speedup vs baseline: 1.2654x; 1.1155x over previous
#include <cuda_runtime.h>
#include <cuda_bf16.h>
#include <cstdint>

// ---------------- problem constants ----------------
#define LSEQ 4096
#define HDIM 512
#define PDIM 256
#define N2P  512          // 2*PDIM (re/im interleaved)
#define KDIM 512
#define TCH  64           // scan chunk length
#define NCH  (LSEQ/TCH)   // 64 chunks
#define MAXB 8

// ---------------- scratch (no allocations allowed) ----------------
__device__ __align__(16) float  g_buf[(size_t)MAXB * LSEQ * N2P];        // Bu fp32
__device__ __align__(16) __nv_bfloat16 g_xh[(size_t)MAXB * LSEQ * HDIM]; // x hi
__device__ __align__(16) __nv_bfloat16 g_xl[(size_t)MAXB * LSEQ * HDIM]; // x lo
__device__ __align__(16) __nv_bfloat16 g_sh[(size_t)MAXB * LSEQ * N2P];  // xs hi
__device__ __align__(16) __nv_bfloat16 g_sl[(size_t)MAXB * LSEQ * N2P];  // xs lo
__device__ float2 g_carry[(size_t)MAXB * NCH * PDIM];
__device__ float2 g_A[PDIM];
__device__ float2 g_AT[PDIM];          // Lambda_bar^TCH
__device__ float2 g_coef[PDIM];
__device__ __align__(16) __nv_bfloat16 g_W1h[(size_t)N2P * KDIM];   // [n=2p][k=h]
__device__ __align__(16) __nv_bfloat16 g_W1l[(size_t)N2P * KDIM];
__device__ __align__(16) __nv_bfloat16 g_W2h[(size_t)HDIM * KDIM];  // [n=h][k=2p]
__device__ __align__(16) __nv_bfloat16 g_W2l[(size_t)HDIM * KDIM];

// ---------------- small device helpers ----------------
__device__ __forceinline__ uint32_t smem_u32(const void* p) {
    uint32_t a;
    asm("{ .reg .u64 t; cvta.to.shared.u64 t, %1; cvt.u32.u64 %0, t; }"
        : "=r"(a) : "l"(p));
    return a;
}
__device__ __forceinline__ void cpasync16(uint32_t dst, const void* src) {
    asm volatile("cp.async.cg.shared.global [%0], [%1], 16;"
                 :: "r"(dst), "l"(src) : "memory");
}
__device__ __forceinline__ void cp_commit() {
    asm volatile("cp.async.commit_group;" ::: "memory");
}
template<int N>
__device__ __forceinline__ void cp_wait() {
    asm volatile("cp.async.wait_group %0;" :: "n"(N) : "memory");
}
__device__ __forceinline__ void ldsm4(uint32_t* r, uint32_t addr) {
    asm volatile("ldmatrix.sync.aligned.m8n8.x4.shared.b16 {%0,%1,%2,%3}, [%4];"
        : "=r"(r[0]), "=r"(r[1]), "=r"(r[2]), "=r"(r[3]) : "r"(addr));
}
__device__ __forceinline__ void mma16816(float* d, const uint32_t* a,
                                         uint32_t b0, uint32_t b1) {
    asm volatile(
        "mma.sync.aligned.m16n8k16.row.col.f32.bf16.bf16.f32 "
        "{%0,%1,%2,%3}, {%4,%5,%6,%7}, {%8,%9}, {%0,%1,%2,%3};"
        : "+f"(d[0]), "+f"(d[1]), "+f"(d[2]), "+f"(d[3])
        : "r"(a[0]), "r"(a[1]), "r"(a[2]), "r"(a[3]), "r"(b0), "r"(b1));
}
__device__ __forceinline__ void split2(float v, __nv_bfloat16& h, __nv_bfloat16& l) {
    h = __float2bfloat16(v);
    l = __float2bfloat16(v - __bfloat162float(h));
}
#define SWZ(o) ((o) ^ (((o) >> 3) & 0x70))

// ---------------- precompute scalars (1 block) ----------------
__global__ void k_precomp_scalar(const float* __restrict__ Lre,
                                 const float* __restrict__ Lim,
                                 const float* __restrict__ lstep) {
    int p = threadIdx.x;
    if (p >= PDIM) return;
    double lr = (double)Lre[p], li = (double)Lim[p];
    float stepf = (float)exp((double)lstep[p]);
    float arf = (float)(lr * (double)stepf);
    float aif = (float)(li * (double)stepf);
    float erf_ = (float)exp((double)arf);
    float cf  = (float)cos((double)aif);
    float sf  = (float)sin((double)aif);
    float2 a = make_float2(erf_ * cf, erf_ * sf);
    g_A[p] = a;
    double ax = (double)a.x, ay = (double)a.y;
    #pragma unroll
    for (int i = 0; i < 6; i++) {          // TCH = 64 = 2^6
        double nx = ax * ax - ay * ay;
        double ny = 2.0 * ax * ay;
        ax = nx; ay = ny;
    }
    g_AT[p] = make_float2((float)ax, (float)ay);
    double nr = (double)a.x - 1.0, ni = (double)a.y;
    double den = lr * lr + li * li;
    g_coef[p] = make_float2((float)((nr * lr + ni * li) / den),
                            (float)((ni * lr - nr * li) / den));
}

// ---------------- build bf16 hi/lo weights, N-major [n][k] ----------------
__global__ void k_precomp_w(const float* __restrict__ Bin,
                            const float* __restrict__ Cin) {
    int t = blockIdx.x * blockDim.x + threadIdx.x;   // over H*P
    if (t >= HDIM * PDIM) return;
    int h = t / PDIM, p = t % PDIM;
    float2 cf = g_coef[p];
    float br = Bin[(p * HDIM + h) * 2 + 0];
    float bi = Bin[(p * HDIM + h) * 2 + 1];
    float wre = cf.x * br - cf.y * bi;
    float wim = cf.x * bi + cf.y * br;
    split2(wre, g_W1h[(size_t)(2 * p) * KDIM + h], g_W1l[(size_t)(2 * p) * KDIM + h]);
    split2(wim, g_W1h[(size_t)(2 * p + 1) * KDIM + h], g_W1l[(size_t)(2 * p + 1) * KDIM + h]);
    float cr = Cin[(h * PDIM + p) * 2 + 0];
    float ci = Cin[(h * PDIM + p) * 2 + 1];
    split2( 2.0f * cr, g_W2h[(size_t)h * KDIM + 2 * p],     g_W2l[(size_t)h * KDIM + 2 * p]);
    split2(-2.0f * ci, g_W2h[(size_t)h * KDIM + 2 * p + 1], g_W2l[(size_t)h * KDIM + 2 * p + 1]);
}

// ---------------- x -> bf16 hi/lo ----------------
__global__ void k_cvt_x(const float* __restrict__ x, int n4) {
    int i = blockIdx.x * blockDim.x + threadIdx.x;
    if (i >= n4) return;
    float4 v = ((const float4*)x)[i];
    __nv_bfloat16 h0, h1, h2, h3, l0, l1, l2, l3;
    split2(v.x, h0, l0); split2(v.y, h1, l1);
    split2(v.z, h2, l2); split2(v.w, h3, l3);
    __nv_bfloat162 ph0 = __nv_bfloat162(h0, h1), ph1 = __nv_bfloat162(h2, h3);
    __nv_bfloat162 pl0 = __nv_bfloat162(l0, l1), pl1 = __nv_bfloat162(l2, l3);
    ((uint2*)g_xh)[i] = make_uint2(*(uint32_t*)&ph0, *(uint32_t*)&ph1);
    ((uint2*)g_xl)[i] = make_uint2(*(uint32_t*)&pl0, *(uint32_t*)&pl1);
}

// ---------------- mma.sync bf16 split GEMM: C[M,512] = A @ W^T (+ D*x) -------
// A: bf16 hi/lo [M][512] row-major; W: bf16 hi/lo [512][512] N-major [n][k].
// 128x128 CTA tile, K-chunk 64, 3-stage cp.async pipeline, SW128 smem,
// ldmatrix fragments. 512 threads = 16 warps (4x4), warp tile 32(M) x 32(N).
// Stage layout (64KB): Ah@0, Al@16K, Wh@32K, Wl@48K; 128 rows x 128B, swizzled.
#define GSTG 65536
#define GSMT (3 * GSTG)

template<int EPI>
__global__ void __launch_bounds__(512)
k_mmagemm(const __nv_bfloat16* __restrict__ Ahg, const __nv_bfloat16* __restrict__ Alg,
          const __nv_bfloat16* __restrict__ Whg, const __nv_bfloat16* __restrict__ Wlg,
          float* __restrict__ Cg, const float* __restrict__ Dv,
          const float* __restrict__ Xg) {
    extern __shared__ __align__(128) char smem[];
    uint32_t sb = smem_u32(smem);
    int tid = threadIdx.x, wid = tid >> 5, lid = tid & 31;
    int g = lid >> 2, t = lid & 3;
    int wm = (wid & 3) * 32, wn = (wid >> 2) * 32;
    size_t brow = (size_t)blockIdx.y * 128;
    size_t bcol = (size_t)blockIdx.x * 128;

    // gmem -> smem mapping: 4 threads per 128B row, 2 x 16B each
    int lrow = tid >> 2;
    uint32_t lseg = (uint32_t)(tid & 3) * 32;
    const char* srcAh = (const char*)(Ahg + (brow + lrow) * KDIM) + lseg;
    const char* srcAl = (const char*)(Alg + (brow + lrow) * KDIM) + lseg;
    const char* srcWh = (const char*)(Whg + (bcol + lrow) * KDIM) + lseg;
    const char* srcWl = (const char*)(Wlg + (bcol + lrow) * KDIM) + lseg;
    uint32_t dbase = (uint32_t)lrow * 128 + lseg;

    // ldmatrix lane addressing
    int r15 = lid & 15;
    uint32_t c16 = ((uint32_t)(lid >> 4)) * 16;   // matrices 2,3 take k bytes +16
    uint32_t xr  = ((uint32_t)(lid & 7)) * 16;    // SW128 row-phase XOR

    float acc[2][4][4];
    #pragma unroll
    for (int mt = 0; mt < 2; mt++)
        #pragma unroll
        for (int nt = 0; nt < 4; nt++)
            #pragma unroll
            for (int j = 0; j < 4; j++) acc[mt][nt][j] = 0.f;

    auto load_stage = [&](int c, int s) {
        uint32_t st = sb + (uint32_t)s * GSTG;
        size_t ko = (size_t)c * 128;   // 64 bf16 = 128B along K per chunk
        #pragma unroll
        for (int i = 0; i < 2; i++) {
            uint32_t d = SWZ(dbase + i * 16);
            cpasync16(st +         d, srcAh + ko + i * 16);
            cpasync16(st + 16384 + d, srcAl + ko + i * 16);
            cpasync16(st + 32768 + d, srcWh + ko + i * 16);
            cpasync16(st + 49152 + d, srcWl + ko + i * 16);
        }
        cp_commit();
    };

    auto compute_stage = [&](int s) {
        uint32_t st = sb + (uint32_t)s * GSTG;
        #pragma unroll
        for (int ks = 0; ks < 4; ks++) {
            uint32_t col = ((uint32_t)ks * 32 + c16) ^ xr;   // within 128B row
            uint32_t ah[2][4], al[2][4];
            #pragma unroll
            for (int mt = 0; mt < 2; mt++) {
                uint32_t rb = st + (uint32_t)(wm + mt * 16 + r15) * 128;
                ldsm4(ah[mt], rb + col);             // A hi
                ldsm4(al[mt], rb + 16384 + col);     // A lo
            }
            #pragma unroll
            for (int pr = 0; pr < 2; pr++) {
                uint32_t bh[4], bl[4];
                uint32_t rb = st + 32768 + (uint32_t)(wn + pr * 16 + r15) * 128;
                ldsm4(bh, rb + col);                 // W hi
                ldsm4(bl, rb + 16384 + col);         // W lo
                #pragma unroll
                for (int mt = 0; mt < 2; mt++)
                    #pragma unroll
                    for (int sub = 0; sub < 2; sub++) {
                        float* d = acc[mt][pr * 2 + sub];
                        mma16816(d, ah[mt], bh[sub], bh[sub + 2]);
                        mma16816(d, ah[mt], bl[sub], bl[sub + 2]);
                        mma16816(d, al[mt], bh[sub], bh[sub + 2]);
                    }
            }
        }
    };

    // 3-stage pipeline over 8 K-chunks
    load_stage(0, 0);
    load_stage(1, 1);
    cp_wait<1>();
    __syncthreads();
    #pragma unroll 1
    for (int c = 0; c < 8; c++) {
        if (c + 2 < 8) load_stage(c + 2, (c + 2) % 3);
        compute_stage(c % 3);
        if (c + 1 < 8) {
            cp_wait<1>();
            __syncthreads();
        }
    }

    // epilogue: accum -> gmem fp32 (+ D*x)
    #pragma unroll
    for (int mt = 0; mt < 2; mt++) {
        size_t r0 = brow + wm + mt * 16 + g;
        size_t r1 = r0 + 8;
        #pragma unroll
        for (int nt = 0; nt < 4; nt++) {
            size_t col = bcol + wn + nt * 8 + t * 2;
            float2 v0 = make_float2(acc[mt][nt][0], acc[mt][nt][1]);
            float2 v1 = make_float2(acc[mt][nt][2], acc[mt][nt][3]);
            if (EPI) {
                float2 d  = *(const float2*)(Dv + col);
                float2 x0 = *(const float2*)(Xg + r0 * 512 + col);
                float2 x1 = *(const float2*)(Xg + r1 * 512 + col);
                v0.x = fmaf(d.x, x0.x, v0.x); v0.y = fmaf(d.y, x0.y, v0.y);
                v1.x = fmaf(d.x, x1.x, v1.x); v1.y = fmaf(d.y, x1.y, v1.y);
            }
            *(float2*)(Cg + r0 * 512 + col) = v0;
            *(float2*)(Cg + r1 * 512 + col) = v1;
        }
    }
}

// ---------------- chunk carry pass (read-only over Bu) ----------------
__global__ void k_scan_carry() {
    int p  = threadIdx.x;
    int ch = blockIdx.x;
    int b  = blockIdx.y;
    float2 a = g_A[p];
    const float2* buf = (const float2*)g_buf;
    size_t base = ((size_t)b * LSEQ + (size_t)ch * TCH) * PDIM + p;
    float sx = 0.f, sy = 0.f;
    #pragma unroll 4
    for (int i = 0; i < TCH; i++) {
        float2 v = buf[base + (size_t)i * PDIM];
        float nx = fmaf(a.x, sx, fmaf(-a.y, sy, v.x));
        float ny = fmaf(a.x, sy, fmaf( a.y, sx, v.y));
        sx = nx; sy = ny;
    }
    g_carry[((size_t)b * NCH + ch) * PDIM + p] = make_float2(sx, sy);
}

// ---------------- exclusive scan over chunk carries ----------------
__global__ void k_scan_carries() {
    int p = threadIdx.x;
    int b = blockIdx.x;
    float2 aT = g_AT[p];
    float sx = 0.f, sy = 0.f;
    for (int j = 0; j < NCH; j++) {
        size_t idx = ((size_t)b * NCH + j) * PDIM + p;
        float2 t = g_carry[idx];
        g_carry[idx] = make_float2(sx, sy);
        float nx = fmaf(aT.x, sx, fmaf(-aT.y, sy, t.x));
        float ny = fmaf(aT.x, sy, fmaf( aT.y, sx, t.y));
        sx = nx; sy = ny;
    }
}

// ---------------- full local scan seeded by carry + convert to bf16 ---------
__global__ void k_fixup_cvt() {
    int p  = threadIdx.x;
    int ch = blockIdx.x;
    int b  = blockIdx.y;
    float2 s = g_carry[((size_t)b * NCH + ch) * PDIM + p];   // exclusive prefix
    float2 a = g_A[p];
    const float2* buf = (const float2*)g_buf;
    size_t rbase = (size_t)b * LSEQ + (size_t)ch * TCH;
    #pragma unroll 4
    for (int i = 0; i < TCH; i++) {
        float2 v = buf[(rbase + i) * PDIM + p];
        float nx = fmaf(a.x, s.x, fmaf(-a.y, s.y, v.x));
        float ny = fmaf(a.x, s.y, fmaf( a.y, s.x, v.y));
        s.x = nx; s.y = ny;
        __nv_bfloat16 hr, lr, hi, li;
        split2(s.x, hr, lr);
        split2(s.y, hi, li);
        __nv_bfloat162 ph = __nv_bfloat162(hr, hi);
        __nv_bfloat162 pl = __nv_bfloat162(lr, li);
        size_t o = (rbase + i) * N2P + 2 * p;
        *(uint32_t*)(g_sh + o) = *(uint32_t*)&ph;
        *(uint32_t*)(g_sl + o) = *(uint32_t*)&pl;
    }
}

// ---------------- launch ----------------
extern "C" void kernel_launch(void* const* d_in, const int* in_sizes, int n_in,
                              void* d_out, int out_size) {
    const float* x   = (const float*)d_in[0];
    const float* Lre = (const float*)d_in[1];
    const float* Lim = (const float*)d_in[2];
    const float* Bin = (const float*)d_in[3];
    const float* Cin = (const float*)d_in[4];
    const float* Dv  = (const float*)d_in[5];
    const float* ls  = (const float*)d_in[6];
    float* y = (float*)d_out;
    (void)n_in; (void)out_size;

    int Bsz = in_sizes[0] / (LSEQ * HDIM);
    if (Bsz > MAXB) Bsz = MAXB;
    int M = Bsz * LSEQ;

    float *bufp = nullptr;
    __nv_bfloat16 *xh, *xl, *sh, *sl, *w1h, *w1l, *w2h, *w2l;
    cudaGetSymbolAddress((void**)&bufp, g_buf);
    cudaGetSymbolAddress((void**)&xh,  g_xh);
    cudaGetSymbolAddress((void**)&xl,  g_xl);
    cudaGetSymbolAddress((void**)&sh,  g_sh);
    cudaGetSymbolAddress((void**)&sl,  g_sl);
    cudaGetSymbolAddress((void**)&w1h, g_W1h);
    cudaGetSymbolAddress((void**)&w1l, g_W1l);
    cudaGetSymbolAddress((void**)&w2h, g_W2h);
    cudaGetSymbolAddress((void**)&w2l, g_W2l);

    cudaFuncSetAttribute(k_mmagemm<0>, cudaFuncAttributeMaxDynamicSharedMemorySize, GSMT);
    cudaFuncSetAttribute(k_mmagemm<1>, cudaFuncAttributeMaxDynamicSharedMemorySize, GSMT);

    k_precomp_scalar<<<1, 256>>>(Lre, Lim, ls);
    k_precomp_w<<<(HDIM * PDIM + 255) / 256, 256>>>(Bin, Cin);

    int n4 = M * HDIM / 4;
    k_cvt_x<<<(n4 + 255) / 256, 256>>>(x, n4);

    // GEMM1: Bu = x @ W1  -> g_buf (fp32)
    dim3 g1(N2P / 128, M / 128);
    k_mmagemm<0><<<g1, 512, GSMT>>>(xh, xl, w1h, w1l, bufp, nullptr, nullptr);

    // scan
    dim3 gs(NCH, Bsz);
    k_scan_carry<<<gs, PDIM>>>();
    k_scan_carries<<<Bsz, PDIM>>>();
    k_fixup_cvt<<<gs, PDIM>>>();

    // GEMM2: y = xs @ W2 + D*x
    dim3 g2(HDIM / 128, M / 128);
    k_mmagemm<1><<<g2, 512, GSMT>>>(sh, sl, w2h, w2l, y, Dv, x);
}